// round 16
// baseline (speedup 1.0000x reference)
#include <cuda_runtime.h>
#include <cuda_fp16.h>
#include <math.h>
#include <cstdint>

#define Bq   8
#define Nq   2048
#define Dq   1024
#define Eq   8
#define Hq   4096
#define CAP  320
#define NTOK (Bq*Nq)
#define OUT_MAIN ((size_t)NTOK*Dq)

// ---- scratch (same set; d_h carved into fp16 regions, footprint unchanged) ----
// d_h as __half[167,772,160]:
//   [0, 83886080)            hidden (phase1 out, phase2 A in)
//   [83886080, 117440512)    w1h  [e][n(Hq)][k(Dq)]
//   [117440512, 150994944)   w2h  [e][n(Dq)][k(Hq)]
//   [150994944, 167772160)   xh   [tok][d]
#define HID_OFF  0ULL
#define W1H_OFF  83886080ULL
#define W2H_OFF  117440512ULL
#define XH_OFF   150994944ULL

__device__ int   d_meta[NTOK];
__device__ float d_g1[NTOK];
__device__ float d_g2[NTOK];
__device__ int   d_a1[NTOK];
__device__ int   d_a2[NTOK];
__device__ float d_proxy[Bq*Eq];
__device__ int   d_slotTok[Eq*Bq*CAP];
__device__ float d_h [(size_t)Eq*Bq*CAP*Hq];
__device__ float d_eo[(size_t)Eq*Bq*CAP*Dq];

// ---------------- helpers ----------------
__device__ __forceinline__ uint32_t smem_u32(const void* p) {
    uint32_t a;
    asm("{ .reg .u64 t; cvta.to.shared.u64 t, %1; cvt.u32.u64 %0, t; }" : "=r"(a) : "l"(p));
    return a;
}
__device__ __forceinline__ uint32_t packh2(float lo, float hi) {
    uint32_t r;
    asm("cvt.rn.f16x2.f32 %0, %1, %2;" : "=r"(r) : "f"(hi), "f"(lo));
    return r;
}
__device__ __forceinline__ void mma_fp16(float* d, const uint32_t* a, const uint32_t* b) {
    asm volatile(
        "mma.sync.aligned.m16n8k16.row.col.f32.f16.f16.f32 "
        "{%0,%1,%2,%3}, {%4,%5,%6,%7}, {%8,%9}, {%0,%1,%2,%3};\n"
        : "+f"(d[0]), "+f"(d[1]), "+f"(d[2]), "+f"(d[3])
        : "r"(a[0]), "r"(a[1]), "r"(a[2]), "r"(a[3]), "r"(b[0]), "r"(b[1]));
}
__device__ __forceinline__ void ldsm4(uint32_t* r, uint32_t addr) {
    asm volatile("ldmatrix.sync.aligned.m8n8.x4.shared.b16 {%0,%1,%2,%3}, [%4];"
        : "=r"(r[0]), "=r"(r[1]), "=r"(r[2]), "=r"(r[3]) : "r"(addr));
}

// ---------------- init ----------------
__global__ void init_kernel() {
    int t = threadIdx.x;
    if (t < Bq*Eq) d_proxy[t] = 0.f;
}

// ---------------- convert x -> fp16 into xh region ----------------
__global__ __launch_bounds__(256) void conv_x_h(const float* __restrict__ x) {
    __half* xh = (__half*)d_h + XH_OFF;
    size_t i = ((size_t)blockIdx.x * 256 + threadIdx.x) * 4;
    float4 v = *(const float4*)(x + i);
    uint2 q;
    q.x = packh2(v.x, v.y);
    q.y = packh2(v.z, v.w);
    *(uint2*)(xh + i) = q;
}

// ---------------- convert + transpose weights: Wh[e][n][k] = rn16(W[e][k][n]) ----------------
template<int Kd, int Nc, int WHICH>
__global__ __launch_bounds__(256) void conv_w_h(const float* __restrict__ W) {
    __half* Wt = (__half*)d_h + (WHICH == 1 ? W1H_OFF : W2H_OFF);
    __shared__ float t[32][33];
    const int e  = blockIdx.z;
    const int k0 = blockIdx.y * 32, n0 = blockIdx.x * 32;
    const float* src = W + (size_t)e * Kd * Nc;
    __half* dst = Wt + (size_t)e * Kd * Nc;
    const int lx = threadIdx.x & 31, ly = threadIdx.x >> 5;
    #pragma unroll
    for (int yy = ly; yy < 32; yy += 8)
        t[yy][lx] = src[(size_t)(k0 + yy) * Nc + n0 + lx];
    __syncthreads();
    #pragma unroll
    for (int yy = ly; yy < 32; yy += 8)
        dst[(size_t)(n0 + yy) * Kd + k0 + lx] = __float2half_rn(t[lx][yy]);
}

// ---------------- gating ----------------
__global__ __launch_bounds__(256) void gating_kernel(
    const float* __restrict__ x, const float* __restrict__ wg,
    const float* __restrict__ rnd)
{
    __shared__ float s_wg[Eq][Dq];
    __shared__ float s_proxy[Eq];
    int tid = threadIdx.x;
    for (int f = tid; f < Dq*Eq; f += 256) {
        int d = f >> 3, e = f & 7;
        s_wg[e][d] = wg[f];
    }
    if (tid < Eq) s_proxy[tid] = 0.f;
    __syncthreads();

    int warp = tid >> 5, lane = tid & 31;
    int tok  = blockIdx.x * 8 + warp;
    const float* xp = x + (size_t)tok * Dq;

    float acc[Eq];
    #pragma unroll
    for (int e = 0; e < Eq; ++e) acc[e] = 0.f;
    #pragma unroll 4
    for (int i = 0; i < Dq/32; ++i) {
        float xv = xp[i*32 + lane];
        #pragma unroll
        for (int e = 0; e < Eq; ++e) acc[e] += xv * s_wg[e][i*32 + lane];
    }
    #pragma unroll
    for (int off = 16; off; off >>= 1)
        #pragma unroll
        for (int e = 0; e < Eq; ++e)
            acc[e] += __shfl_down_sync(0xffffffffu, acc[e], off);

    if (lane == 0) {
        float mx = acc[0];
        #pragma unroll
        for (int e = 1; e < Eq; ++e) mx = fmaxf(mx, acc[e]);
        float raw[Eq]; float s = 0.f;
        #pragma unroll
        for (int e = 0; e < Eq; ++e) { raw[e] = expf(acc[e] - mx); s += raw[e]; }
        float inv = 1.f / s;
        #pragma unroll
        for (int e = 0; e < Eq; ++e) raw[e] *= inv;
        int i1 = 0; float g1 = raw[0];
        #pragma unroll
        for (int e = 1; e < Eq; ++e) if (raw[e] > g1) { g1 = raw[e]; i1 = e; }
        int i2 = -1; float g2 = -1.f;
        #pragma unroll
        for (int e = 0; e < Eq; ++e) if (e != i1 && raw[e] > g2) { g2 = raw[e]; i2 = e; }
        float denom = g1 + g2 + 1e-9f;
        float g1n = g1 / denom, g2n = g2 / denom;
        int keep2 = (rnd[tok] < (g2n / 0.2f)) ? 1 : 0;
        d_meta[tok] = i1 | (i2 << 4) | (keep2 << 8);
        d_g1[tok] = g1n;
        d_g2[tok] = g2n;
        #pragma unroll
        for (int e = 0; e < Eq; ++e) atomicAdd(&s_proxy[e], raw[e]);
    }
    __syncthreads();
    if (tid < Eq) {
        int b = (blockIdx.x * 8) >> 11;
        atomicAdd(&d_proxy[b*Eq + tid], s_proxy[tid]);
    }
}

// ---------------- scan ----------------
__global__ void scan_kernel(float* __restrict__ dout, int out_size)
{
    __shared__ int   s_meta[2048];
    __shared__ float s_red[64];
    int t = threadIdx.x;
    int b = t >> 3, e = t & 7;
    int g = e * Bq + b;
    for (int j = 0; j < CAP; ++j) d_slotTok[g*CAP + j] = -1;
    int c1 = 0;
    for (int ch = 0; ch < 8; ++ch) {
        __syncthreads();
        for (int i = t; i < 2048; i += 64) {
            int bb = i >> 8, ii = i & 255;
            s_meta[i] = d_meta[bb*Nq + ch*256 + ii];
        }
        __syncthreads();
        for (int ii = 0; ii < 256; ++ii) {
            int meta = s_meta[b*256 + ii];
            if ((meta & 15) == e) {
                int n = ch*256 + ii;
                if (c1 < CAP) {
                    d_slotTok[g*CAP + c1] = n;
                    d_a1[b*Nq + n] = (e << 10) | c1;
                } else d_a1[b*Nq + n] = -1;
                c1++;
            }
        }
    }
    int c1raw = c1;
    int pos = (c1 < CAP) ? c1 : CAP;
    for (int ch = 0; ch < 8; ++ch) {
        __syncthreads();
        for (int i = t; i < 2048; i += 64) {
            int bb = i >> 8, ii = i & 255;
            s_meta[i] = d_meta[bb*Nq + ch*256 + ii];
        }
        __syncthreads();
        for (int ii = 0; ii < 256; ++ii) {
            int meta = s_meta[b*256 + ii];
            if (((meta >> 4) & 15) == e) {
                int n = ch*256 + ii;
                if ((meta >> 8) & 1) {
                    if (pos < CAP) {
                        d_slotTok[g*CAP + pos] = n;
                        d_a2[b*Nq + n] = (e << 10) | pos;
                    } else d_a2[b*Nq + n] = -1;
                    pos++;
                } else d_a2[b*Nq + n] = -1;
            }
        }
    }
    s_red[t] = (d_proxy[b*Eq + e] / (float)Nq) * ((float)c1raw / (float)Nq);
    __syncthreads();
    if (t == 0) {
        float s = 0.f;
        for (int i = 0; i < 64; ++i) s += s_red[i];
        if ((size_t)out_size > OUT_MAIN) dout[OUT_MAIN] = s * 0.01f;
    }
}

// ---------------- fp16 mma.sync grouped GEMM: CTA 128x256, warp 64x64, K-chunk 64 ----------------
// 8 warps (2m x 4n), mma m16n8k16, 2-stage double buffer.
// SMEM: sA[2][16384] @0      (A[row(128)][k(64) half], off=row*128+16*(slot^(row&7)))
//       sB[2][32768] @32768  (B[n(256)][k(64) half], same swizzle)
//       sPtr @98304 (1KB), sBias @99328 (1KB) -> total 100352
// ALL staging is pure fp16 LDG.128 -> STS.128 (operands pre-converted in d_h regions).
#define SMEM_FFN 100352
#define FFN_THREADS 256

template<int PHASE>
__global__ __launch_bounds__(FFN_THREADS, 1) void ffn_mma(const float* __restrict__ Bias)
{
    constexpr int Kdim  = (PHASE == 1) ? Dq : Hq;
    constexpr int Ncols = (PHASE == 1) ? Hq : Dq;
    constexpr int NCH   = Kdim / 64;

    extern __shared__ char smem[];
    const __half** sPtr  = (const __half**)(smem + 98304);
    float*         sBias = (float*)(smem + 99328);

    const int tid  = threadIdx.x;
    const int wid  = tid >> 5, lane = tid & 31;
    const int g8   = lane >> 2, tg = lane & 3;
    const int n0   = blockIdx.x * 256;
    const int m0   = blockIdx.y * 128;
    const int grp  = blockIdx.z;
    const int e    = grp >> 3, b = grp & 7;
    const int wm   = wid & 1, wn = wid >> 1;       // 2m x 4n warps, 64x64 tiles
    const bool active = (m0 + wm*64) < CAP;

    if (tid < 128) {
        int c = m0 + tid;
        const __half* p = nullptr;
        if (c < CAP) {
            if (PHASE == 1) {
                int tok = d_slotTok[grp*CAP + c];
                if (tok >= 0) p = (const __half*)d_h + XH_OFF + ((size_t)(b*Nq) + tok) * Dq;
            } else {
                p = (const __half*)d_h + HID_OFF + ((size_t)grp*CAP + c) * Hq;
            }
        }
        sPtr[tid] = p;
    }
    sBias[tid] = Bias[(size_t)e * Ncols + n0 + tid];
    __syncthreads();

    const uint32_t sb = smem_u32(smem);

    // A fill: arow = tid & 127, ahalf = tid >> 7 -> slots ahalf*4 + {0..3}
    const int arow  = tid & 127;
    const int ahalf = tid >> 7;
    const __half* aPtr = sPtr[arow];
    uint32_t stRelA[4];
    #pragma unroll
    for (int i = 0; i < 4; ++i)
        stRelA[i] = (uint32_t)(arow*128 + 16*((ahalf*4 + i) ^ (arow & 7)));

    // B fill: bn = tid (0..255), slots 0..7; Wh layout [e][n][k] fp16
    const int bn = tid;
    const __half* Wg = (const __half*)d_h + (PHASE == 1 ? W1H_OFF : W2H_OFF)
                     + (size_t)e * Kdim * Ncols + (size_t)(n0 + bn) * Kdim;
    uint32_t stRelB[8];
    #pragma unroll
    for (int s = 0; s < 8; ++s)
        stRelB[s] = (uint32_t)(bn*128 + 16*(s ^ (bn & 7)));

    uint4 rAh[4], rBh[8];

    #define LDT(ch) do { \
        _Pragma("unroll") \
        for (int i = 0; i < 4; ++i) { \
            if (aPtr) rAh[i] = *(const uint4*)(aPtr + (ch)*64 + (ahalf*4 + i)*8); \
            else      rAh[i] = make_uint4(0u, 0u, 0u, 0u); \
        } \
        _Pragma("unroll") \
        for (int s = 0; s < 8; ++s) \
            rBh[s] = *(const uint4*)(Wg + (ch)*64 + s*8); \
    } while (0)
    #define STT(buf) do { \
        _Pragma("unroll") \
        for (int i = 0; i < 4; ++i) \
            *(uint4*)(smem + (buf)*16384 + stRelA[i]) = rAh[i]; \
        _Pragma("unroll") \
        for (int s = 0; s < 8; ++s) \
            *(uint4*)(smem + 32768 + (buf)*32768 + stRelB[s]) = rBh[s]; \
    } while (0)

    // ldmatrix geometry (byte-identical to r15-validated fp16 pattern)
    const int hiA = lane >> 4;
    const uint32_t aBaseRel = (uint32_t)(wm*64 + ((lane>>3)&1)*8 + (lane&7)) * 128u;
    const uint32_t bBaseRel = (uint32_t)(wn*64 + (lane>>4)*8 + (lane&7)) * 128u;
    uint32_t aSw[4], bSw[4];
    #pragma unroll
    for (int ks = 0; ks < 4; ++ks) {
        aSw[ks] = 16u * (uint32_t)((2*ks + hiA) ^ (lane & 7));
        bSw[ks] = 16u * (uint32_t)((2*ks + ((lane>>3)&1)) ^ (lane & 7));
    }

    float acc[4][8][4];
    #pragma unroll
    for (int mi = 0; mi < 4; ++mi)
        #pragma unroll
        for (int ni = 0; ni < 8; ++ni)
            #pragma unroll
            for (int q = 0; q < 4; ++q) acc[mi][ni][q] = 0.f;

    LDT(0);
    STT(0);
    __syncthreads();

    for (int ch = 0; ch < NCH; ++ch) {
        const int buf = ch & 1;
        if (ch + 1 < NCH) LDT(ch + 1);

        if (active) {
            const uint32_t aOff = sb + (uint32_t)(buf*16384);
            const uint32_t bOff = sb + 32768u + (uint32_t)(buf*32768);
            #pragma unroll
            for (int ks = 0; ks < 4; ++ks) {
                uint32_t af[4][4], bf[4][4];
                const uint32_t ao = aOff + aBaseRel + aSw[ks];
                const uint32_t bo = bOff + bBaseRel + bSw[ks];
                #pragma unroll
                for (int mi = 0; mi < 4; ++mi)
                    ldsm4(af[mi], ao + (uint32_t)(mi*2048));
                #pragma unroll
                for (int j = 0; j < 4; ++j)
                    ldsm4(bf[j], bo + (uint32_t)(j*2048));
                #pragma unroll
                for (int mi = 0; mi < 4; ++mi)
                    #pragma unroll
                    for (int j = 0; j < 4; ++j) {
                        mma_fp16(acc[mi][2*j],     af[mi], &bf[j][0]);
                        mma_fp16(acc[mi][2*j + 1], af[mi], &bf[j][2]);
                    }
            }
        }

        if (ch + 1 < NCH) STT(buf ^ 1);
        __syncthreads();
    }
    #undef LDT
    #undef STT

    // epilogue: bias (+GELU phase1 -> fp16 hidden; phase2 -> fp32 d_eo)
    #pragma unroll
    for (int mi = 0; mi < 4; ++mi) {
        #pragma unroll
        for (int h = 0; h < 2; ++h) {
            int c = m0 + wm*64 + mi*16 + g8 + h*8;
            if (c < CAP) {
                #pragma unroll
                for (int ni = 0; ni < 8; ++ni) {
                    int col = wn*64 + ni*8 + 2*tg;
                    float v0 = acc[mi][ni][2*h]     + sBias[col];
                    float v1 = acc[mi][ni][2*h + 1] + sBias[col + 1];
                    if (PHASE == 1) {
                        v0 = 0.5f * v0 * (1.0f + erff(v0 * 0.70710678118654752f));
                        v1 = 0.5f * v1 * (1.0f + erff(v1 * 0.70710678118654752f));
                        __half* orowH = (__half*)d_h + HID_OFF + ((size_t)grp*CAP + c) * Hq + n0;
                        *(uint32_t*)(orowH + col) = packh2(v0, v1);
                    } else {
                        float* orow = d_eo + ((size_t)grp*CAP + c) * Dq + n0;
                        float2 v = make_float2(v0, v1);
                        *(float2*)(orow + col) = v;
                    }
                }
            }
        }
    }
}

// ---------------- combine ----------------
__global__ __launch_bounds__(256) void combine_kernel(float* __restrict__ out)
{
    int tok = blockIdx.x;
    int b   = tok >> 11;
    int a1  = d_a1[tok], a2 = d_a2[tok];
    float g1 = d_g1[tok], g2 = d_g2[tok];
    int off = threadIdx.x * 4;

    float4 v = make_float4(0.f, 0.f, 0.f, 0.f);
    if (a1 >= 0) {
        size_t row = ((size_t)((a1 >> 10) * Bq + b)) * CAP + (a1 & 1023);
        const float4 s = *(const float4*)(d_eo + row * Dq + off);
        v.x = g1 * s.x; v.y = g1 * s.y; v.z = g1 * s.z; v.w = g1 * s.w;
    }
    if (a2 >= 0) {
        size_t row = ((size_t)((a2 >> 10) * Bq + b)) * CAP + (a2 & 1023);
        const float4 s = *(const float4*)(d_eo + row * Dq + off);
        v.x += g2 * s.x; v.y += g2 * s.y; v.z += g2 * s.z; v.w += g2 * s.w;
    }
    *(float4*)(out + (size_t)tok * Dq + off) = v;
}

// ---------------- launch ----------------
extern "C" void kernel_launch(void* const* d_in, const int* in_sizes, int n_in,
                              void* d_out, int out_size)
{
    const float* x  = (const float*)d_in[0];
    const float* wg = (const float*)d_in[1];
    const float* w1 = (const float*)d_in[2];
    const float* b1 = (const float*)d_in[3];
    const float* w2 = (const float*)d_in[4];
    const float* b2 = (const float*)d_in[5];
    const float* rp = (const float*)d_in[6];
    float* out = (float*)d_out;

    cudaFuncSetAttribute(ffn_mma<1>, cudaFuncAttributeMaxDynamicSharedMemorySize, SMEM_FFN);
    cudaFuncSetAttribute(ffn_mma<2>, cudaFuncAttributeMaxDynamicSharedMemorySize, SMEM_FFN);

    init_kernel<<<1, 64>>>();
    gating_kernel<<<NTOK/8, 256>>>(x, wg, rp);
    scan_kernel<<<1, 64>>>(out, out_size);
    conv_x_h<<<NTOK*Dq/1024, 256>>>(x);
    conv_w_h<Dq, Hq, 1><<<dim3(Hq/32, Dq/32, Eq), 256>>>(w1);
    conv_w_h<Hq, Dq, 2><<<dim3(Dq/32, Hq/32, Eq), 256>>>(w2);

    ffn_mma<1><<<dim3(Hq/256, 3, Eq*Bq), FFN_THREADS, SMEM_FFN>>>(b1);
    ffn_mma<2><<<dim3(Dq/256, 3, Eq*Bq), FFN_THREADS, SMEM_FFN>>>(b2);

    combine_kernel<<<NTOK, 256>>>(out);
}

// round 17
// speedup vs baseline: 1.3386x; 1.3386x over previous
#include <cuda_runtime.h>
#include <cuda_fp16.h>
#include <math.h>
#include <cstdint>

#define Bq   8
#define Nq   2048
#define Dq   1024
#define Eq   8
#define Hq   4096
#define CAP  320
#define NTOK (Bq*Nq)
#define OUT_MAIN ((size_t)NTOK*Dq)

// ---- d_h carved into fp16 regions (footprint unchanged vs r5..r15) ----
// d_h as __half[167,772,160]:
//   [0, 83886080)            hidden (phase1 out, phase2 A in)
//   [83886080, 117440512)    w1h  tiled-swizzled blocks (see conv_w_tiled)
//   [117440512, 150994944)   w2h  tiled-swizzled blocks
//   [150994944, 167772160)   xh   [tok][d] fp16
#define HID_OFF  0ULL
#define W1H_OFF  83886080ULL
#define W2H_OFF  117440512ULL
#define XH_OFF   150994944ULL

__device__ int   d_meta[NTOK];
__device__ float d_g1[NTOK];
__device__ float d_g2[NTOK];
__device__ int   d_a1[NTOK];
__device__ int   d_a2[NTOK];
__device__ float d_proxy[Bq*Eq];
__device__ int   d_slotTok[Eq*Bq*CAP];
__device__ float d_h [(size_t)Eq*Bq*CAP*Hq];
__device__ float d_eo[(size_t)Eq*Bq*CAP*Dq];

// ---------------- helpers ----------------
__device__ __forceinline__ uint32_t smem_u32(const void* p) {
    uint32_t a;
    asm("{ .reg .u64 t; cvta.to.shared.u64 t, %1; cvt.u32.u64 %0, t; }" : "=r"(a) : "l"(p));
    return a;
}
__device__ __forceinline__ uint32_t packh2(float lo, float hi) {
    uint32_t r;
    asm("cvt.rn.f16x2.f32 %0, %1, %2;" : "=r"(r) : "f"(hi), "f"(lo));
    return r;
}
__device__ __forceinline__ void mma_fp16(float* d, const uint32_t* a, const uint32_t* b) {
    asm volatile(
        "mma.sync.aligned.m16n8k16.row.col.f32.f16.f16.f32 "
        "{%0,%1,%2,%3}, {%4,%5,%6,%7}, {%8,%9}, {%0,%1,%2,%3};\n"
        : "+f"(d[0]), "+f"(d[1]), "+f"(d[2]), "+f"(d[3])
        : "r"(a[0]), "r"(a[1]), "r"(a[2]), "r"(a[3]), "r"(b[0]), "r"(b[1]));
}
__device__ __forceinline__ void ldsm4(uint32_t* r, uint32_t addr) {
    asm volatile("ldmatrix.sync.aligned.m8n8.x4.shared.b16 {%0,%1,%2,%3}, [%4];"
        : "=r"(r[0]), "=r"(r[1]), "=r"(r[2]), "=r"(r[3]) : "r"(addr));
}

// ---------------- init ----------------
__global__ void init_kernel() {
    int t = threadIdx.x;
    if (t < Bq*Eq) d_proxy[t] = 0.f;
}

// ---------------- convert x -> fp16 into xh region ----------------
__global__ __launch_bounds__(256) void conv_x_h(const float* __restrict__ x) {
    __half* xh = (__half*)d_h + XH_OFF;
    size_t i = ((size_t)blockIdx.x * 256 + threadIdx.x) * 4;
    float4 v = *(const float4*)(x + i);
    uint2 q;
    q.x = packh2(v.x, v.y);
    q.y = packh2(v.z, v.w);
    *(uint2*)(xh + i) = q;
}

// ---- conv weights -> fp16 tiled-swizzled SMEM-image blocks ----
// Block index (e, nt, ch) -> 32KB block at ((e*(Nc/256)+nt)*(Kd/64)+ch)*32768 bytes.
// Within block, (n 0..255, k 0..63) halves at byte n*128 + 16*((k/8)^(n&7)) + (k%8)*2,
// i.e. exactly the GEMM sB stage layout -> GEMM copies the block linearly.
template<int Kd, int Nc, int WHICH>
__global__ __launch_bounds__(256) void conv_w_tiled(const float* __restrict__ W) {
    char* Wt = (char*)((__half*)d_h + (WHICH == 1 ? W1H_OFF : W2H_OFF));
    const int n  = threadIdx.x;
    const int nt = blockIdx.x, ch = blockIdx.y, e = blockIdx.z;
    const float* src = W + (size_t)e * Kd * Nc + (size_t)(ch*64) * Nc + nt*256 + n;
    char* blk = Wt + ((size_t)((e * (Nc/256) + nt) * (Kd/64) + ch)) * 32768 + n*128;

    float v[64];
    #pragma unroll
    for (int k = 0; k < 64; ++k)
        v[k] = src[(size_t)k * Nc];
    #pragma unroll
    for (int s = 0; s < 8; ++s) {
        uint4 q;
        q.x = packh2(v[s*8+0], v[s*8+1]);
        q.y = packh2(v[s*8+2], v[s*8+3]);
        q.z = packh2(v[s*8+4], v[s*8+5]);
        q.w = packh2(v[s*8+6], v[s*8+7]);
        *(uint4*)(blk + 16*(s ^ (n & 7))) = q;
    }
}

// ---------------- gating ----------------
__global__ __launch_bounds__(256) void gating_kernel(
    const float* __restrict__ x, const float* __restrict__ wg,
    const float* __restrict__ rnd)
{
    __shared__ float s_wg[Eq][Dq];
    __shared__ float s_proxy[Eq];
    int tid = threadIdx.x;
    for (int f = tid; f < Dq*Eq; f += 256) {
        int d = f >> 3, e = f & 7;
        s_wg[e][d] = wg[f];
    }
    if (tid < Eq) s_proxy[tid] = 0.f;
    __syncthreads();

    int warp = tid >> 5, lane = tid & 31;
    int tok  = blockIdx.x * 8 + warp;
    const float* xp = x + (size_t)tok * Dq;

    float acc[Eq];
    #pragma unroll
    for (int e = 0; e < Eq; ++e) acc[e] = 0.f;
    #pragma unroll 4
    for (int i = 0; i < Dq/32; ++i) {
        float xv = xp[i*32 + lane];
        #pragma unroll
        for (int e = 0; e < Eq; ++e) acc[e] += xv * s_wg[e][i*32 + lane];
    }
    #pragma unroll
    for (int off = 16; off; off >>= 1)
        #pragma unroll
        for (int e = 0; e < Eq; ++e)
            acc[e] += __shfl_down_sync(0xffffffffu, acc[e], off);

    if (lane == 0) {
        float mx = acc[0];
        #pragma unroll
        for (int e = 1; e < Eq; ++e) mx = fmaxf(mx, acc[e]);
        float raw[Eq]; float s = 0.f;
        #pragma unroll
        for (int e = 0; e < Eq; ++e) { raw[e] = expf(acc[e] - mx); s += raw[e]; }
        float inv = 1.f / s;
        #pragma unroll
        for (int e = 0; e < Eq; ++e) raw[e] *= inv;
        int i1 = 0; float g1 = raw[0];
        #pragma unroll
        for (int e = 1; e < Eq; ++e) if (raw[e] > g1) { g1 = raw[e]; i1 = e; }
        int i2 = -1; float g2 = -1.f;
        #pragma unroll
        for (int e = 0; e < Eq; ++e) if (e != i1 && raw[e] > g2) { g2 = raw[e]; i2 = e; }
        float denom = g1 + g2 + 1e-9f;
        float g1n = g1 / denom, g2n = g2 / denom;
        int keep2 = (rnd[tok] < (g2n / 0.2f)) ? 1 : 0;
        d_meta[tok] = i1 | (i2 << 4) | (keep2 << 8);
        d_g1[tok] = g1n;
        d_g2[tok] = g2n;
        #pragma unroll
        for (int e = 0; e < Eq; ++e) atomicAdd(&s_proxy[e], raw[e]);
    }
    __syncthreads();
    if (tid < Eq) {
        int b = (blockIdx.x * 8) >> 11;
        atomicAdd(&d_proxy[b*Eq + tid], s_proxy[tid]);
    }
}

// ---------------- scan ----------------
__global__ void scan_kernel(float* __restrict__ dout, int out_size)
{
    __shared__ int   s_meta[2048];
    __shared__ float s_red[64];
    int t = threadIdx.x;
    int b = t >> 3, e = t & 7;
    int g = e * Bq + b;
    for (int j = 0; j < CAP; ++j) d_slotTok[g*CAP + j] = -1;
    int c1 = 0;
    for (int ch = 0; ch < 8; ++ch) {
        __syncthreads();
        for (int i = t; i < 2048; i += 64) {
            int bb = i >> 8, ii = i & 255;
            s_meta[i] = d_meta[bb*Nq + ch*256 + ii];
        }
        __syncthreads();
        for (int ii = 0; ii < 256; ++ii) {
            int meta = s_meta[b*256 + ii];
            if ((meta & 15) == e) {
                int n = ch*256 + ii;
                if (c1 < CAP) {
                    d_slotTok[g*CAP + c1] = n;
                    d_a1[b*Nq + n] = (e << 10) | c1;
                } else d_a1[b*Nq + n] = -1;
                c1++;
            }
        }
    }
    int c1raw = c1;
    int pos = (c1 < CAP) ? c1 : CAP;
    for (int ch = 0; ch < 8; ++ch) {
        __syncthreads();
        for (int i = t; i < 2048; i += 64) {
            int bb = i >> 8, ii = i & 255;
            s_meta[i] = d_meta[bb*Nq + ch*256 + ii];
        }
        __syncthreads();
        for (int ii = 0; ii < 256; ++ii) {
            int meta = s_meta[b*256 + ii];
            if (((meta >> 4) & 15) == e) {
                int n = ch*256 + ii;
                if ((meta >> 8) & 1) {
                    if (pos < CAP) {
                        d_slotTok[g*CAP + pos] = n;
                        d_a2[b*Nq + n] = (e << 10) | pos;
                    } else d_a2[b*Nq + n] = -1;
                    pos++;
                } else d_a2[b*Nq + n] = -1;
            }
        }
    }
    s_red[t] = (d_proxy[b*Eq + e] / (float)Nq) * ((float)c1raw / (float)Nq);
    __syncthreads();
    if (t == 0) {
        float s = 0.f;
        for (int i = 0; i < 64; ++i) s += s_red[i];
        if ((size_t)out_size > OUT_MAIN) dout[OUT_MAIN] = s * 0.01f;
    }
}

// ---------------- fp16 mma.sync grouped GEMM: CTA 128x256, warp 64x64, K-chunk 64 ----------------
// 8 warps (2m x 4n), mma m16n8k16, 2-stage double buffer.
// SMEM: sA[2][16384] @0      (A[row(128)][k(64) half], off=row*128+16*(slot^(row&7)))
//       sB[2][32768] @32768  (B stage = linear image of pre-swizzled 32KB weight block)
//       sPtr @98304 (1KB), sBias @99328 (1KB) -> total 100352
// A: fp16 gather (xh / hidden), 4x LDG.128 + 4x STS.128.
// B: pure linear 32KB block copy, 8x LDG.128 (coalesced) + 8x STS.128 (conflict-free).
#define SMEM_FFN 100352
#define FFN_THREADS 256

template<int PHASE>
__global__ __launch_bounds__(FFN_THREADS, 1) void ffn_mma(const float* __restrict__ Bias)
{
    constexpr int Kdim  = (PHASE == 1) ? Dq : Hq;
    constexpr int Ncols = (PHASE == 1) ? Hq : Dq;
    constexpr int NCH   = Kdim / 64;
    constexpr int NT    = Ncols / 256;

    extern __shared__ char smem[];
    const __half** sPtr  = (const __half**)(smem + 98304);
    float*         sBias = (float*)(smem + 99328);

    const int tid  = threadIdx.x;
    const int wid  = tid >> 5, lane = tid & 31;
    const int g8   = lane >> 2, tg = lane & 3;
    const int n0   = blockIdx.x * 256;
    const int m0   = blockIdx.y * 128;
    const int grp  = blockIdx.z;
    const int e    = grp >> 3, b = grp & 7;
    const int wm   = wid & 1, wn = wid >> 1;       // 2m x 4n warps, 64x64 tiles
    const bool active = (m0 + wm*64) < CAP;

    if (tid < 128) {
        int c = m0 + tid;
        const __half* p = nullptr;
        if (c < CAP) {
            if (PHASE == 1) {
                int tok = d_slotTok[grp*CAP + c];
                if (tok >= 0) p = (const __half*)d_h + XH_OFF + ((size_t)(b*Nq) + tok) * Dq;
            } else {
                p = (const __half*)d_h + HID_OFF + ((size_t)grp*CAP + c) * Hq;
            }
        }
        sPtr[tid] = p;
    }
    sBias[tid] = Bias[(size_t)e * Ncols + n0 + tid];
    __syncthreads();

    const uint32_t sb = smem_u32(smem);

    // A fill: arow = tid & 127, ahalf = tid >> 7 -> slots ahalf*4 + {0..3}
    const int arow  = tid & 127;
    const int ahalf = tid >> 7;
    const __half* aPtr = sPtr[arow];
    uint32_t stRelA[4];
    #pragma unroll
    for (int i = 0; i < 4; ++i)
        stRelA[i] = (uint32_t)(arow*128 + 16*((ahalf*4 + i) ^ (arow & 7)));

    // B fill: linear copy of pre-swizzled 32KB block (per chunk)
    const char* Wblk = (const char*)((const __half*)d_h + (PHASE == 1 ? W1H_OFF : W2H_OFF))
                     + ((size_t)((e * NT + blockIdx.x) * NCH)) * 32768;

    uint4 rAh[4], rBh[8];

    #define LDT(ch) do { \
        _Pragma("unroll") \
        for (int i = 0; i < 4; ++i) { \
            if (aPtr) rAh[i] = *(const uint4*)(aPtr + (ch)*64 + (ahalf*4 + i)*8); \
            else      rAh[i] = make_uint4(0u, 0u, 0u, 0u); \
        } \
        const char* bp = Wblk + (size_t)(ch)*32768 + tid*16; \
        _Pragma("unroll") \
        for (int s = 0; s < 8; ++s) \
            rBh[s] = *(const uint4*)(bp + s*4096); \
    } while (0)
    #define STT(buf) do { \
        _Pragma("unroll") \
        for (int i = 0; i < 4; ++i) \
            *(uint4*)(smem + (buf)*16384 + stRelA[i]) = rAh[i]; \
        char* sp = smem + 32768 + (buf)*32768 + tid*16; \
        _Pragma("unroll") \
        for (int s = 0; s < 8; ++s) \
            *(uint4*)(sp + s*4096) = rBh[s]; \
    } while (0)

    // ldmatrix geometry (byte-identical to r15-validated fp16 pattern)
    const int hiA = lane >> 4;
    const uint32_t aBaseRel = (uint32_t)(wm*64 + ((lane>>3)&1)*8 + (lane&7)) * 128u;
    const uint32_t bBaseRel = (uint32_t)(wn*64 + (lane>>4)*8 + (lane&7)) * 128u;
    uint32_t aSw[4], bSw[4];
    #pragma unroll
    for (int ks = 0; ks < 4; ++ks) {
        aSw[ks] = 16u * (uint32_t)((2*ks + hiA) ^ (lane & 7));
        bSw[ks] = 16u * (uint32_t)((2*ks + ((lane>>3)&1)) ^ (lane & 7));
    }

    float acc[4][8][4];
    #pragma unroll
    for (int mi = 0; mi < 4; ++mi)
        #pragma unroll
        for (int ni = 0; ni < 8; ++ni)
            #pragma unroll
            for (int q = 0; q < 4; ++q) acc[mi][ni][q] = 0.f;

    LDT(0);
    STT(0);
    __syncthreads();

    for (int ch = 0; ch < NCH; ++ch) {
        const int buf = ch & 1;
        if (ch + 1 < NCH) LDT(ch + 1);

        if (active) {
            const uint32_t aOff = sb + (uint32_t)(buf*16384);
            const uint32_t bOff = sb + 32768u + (uint32_t)(buf*32768);
            #pragma unroll
            for (int ks = 0; ks < 4; ++ks) {
                uint32_t af[4][4], bf[4][4];
                const uint32_t ao = aOff + aBaseRel + aSw[ks];
                const uint32_t bo = bOff + bBaseRel + bSw[ks];
                #pragma unroll
                for (int mi = 0; mi < 4; ++mi)
                    ldsm4(af[mi], ao + (uint32_t)(mi*2048));
                #pragma unroll
                for (int j = 0; j < 4; ++j)
                    ldsm4(bf[j], bo + (uint32_t)(j*2048));
                #pragma unroll
                for (int mi = 0; mi < 4; ++mi)
                    #pragma unroll
                    for (int j = 0; j < 4; ++j) {
                        mma_fp16(acc[mi][2*j],     af[mi], &bf[j][0]);
                        mma_fp16(acc[mi][2*j + 1], af[mi], &bf[j][2]);
                    }
            }
        }

        if (ch + 1 < NCH) STT(buf ^ 1);
        __syncthreads();
    }
    #undef LDT
    #undef STT

    // epilogue: bias (+GELU phase1 -> fp16 hidden; phase2 -> fp32 d_eo)
    #pragma unroll
    for (int mi = 0; mi < 4; ++mi) {
        #pragma unroll
        for (int h = 0; h < 2; ++h) {
            int c = m0 + wm*64 + mi*16 + g8 + h*8;
            if (c < CAP) {
                #pragma unroll
                for (int ni = 0; ni < 8; ++ni) {
                    int col = wn*64 + ni*8 + 2*tg;
                    float v0 = acc[mi][ni][2*h]     + sBias[col];
                    float v1 = acc[mi][ni][2*h + 1] + sBias[col + 1];
                    if (PHASE == 1) {
                        v0 = 0.5f * v0 * (1.0f + erff(v0 * 0.70710678118654752f));
                        v1 = 0.5f * v1 * (1.0f + erff(v1 * 0.70710678118654752f));
                        __half* orowH = (__half*)d_h + HID_OFF + ((size_t)grp*CAP + c) * Hq + n0;
                        *(uint32_t*)(orowH + col) = packh2(v0, v1);
                    } else {
                        float* orow = d_eo + ((size_t)grp*CAP + c) * Dq + n0;
                        float2 v = make_float2(v0, v1);
                        *(float2*)(orow + col) = v;
                    }
                }
            }
        }
    }
}

// ---------------- combine ----------------
__global__ __launch_bounds__(256) void combine_kernel(float* __restrict__ out)
{
    int tok = blockIdx.x;
    int b   = tok >> 11;
    int a1  = d_a1[tok], a2 = d_a2[tok];
    float g1 = d_g1[tok], g2 = d_g2[tok];
    int off = threadIdx.x * 4;

    float4 v = make_float4(0.f, 0.f, 0.f, 0.f);
    if (a1 >= 0) {
        size_t row = ((size_t)((a1 >> 10) * Bq + b)) * CAP + (a1 & 1023);
        const float4 s = *(const float4*)(d_eo + row * Dq + off);
        v.x = g1 * s.x; v.y = g1 * s.y; v.z = g1 * s.z; v.w = g1 * s.w;
    }
    if (a2 >= 0) {
        size_t row = ((size_t)((a2 >> 10) * Bq + b)) * CAP + (a2 & 1023);
        const float4 s = *(const float4*)(d_eo + row * Dq + off);
        v.x += g2 * s.x; v.y += g2 * s.y; v.z += g2 * s.z; v.w += g2 * s.w;
    }
    *(float4*)(out + (size_t)tok * Dq + off) = v;
}

// ---------------- launch ----------------
extern "C" void kernel_launch(void* const* d_in, const int* in_sizes, int n_in,
                              void* d_out, int out_size)
{
    const float* x  = (const float*)d_in[0];
    const float* wg = (const float*)d_in[1];
    const float* w1 = (const float*)d_in[2];
    const float* b1 = (const float*)d_in[3];
    const float* w2 = (const float*)d_in[4];
    const float* b2 = (const float*)d_in[5];
    const float* rp = (const float*)d_in[6];
    float* out = (float*)d_out;

    cudaFuncSetAttribute(ffn_mma<1>, cudaFuncAttributeMaxDynamicSharedMemorySize, SMEM_FFN);
    cudaFuncSetAttribute(ffn_mma<2>, cudaFuncAttributeMaxDynamicSharedMemorySize, SMEM_FFN);

    init_kernel<<<1, 64>>>();
    gating_kernel<<<NTOK/8, 256>>>(x, wg, rp);
    scan_kernel<<<1, 64>>>(out, out_size);
    conv_x_h<<<NTOK*Dq/1024, 256>>>(x);
    conv_w_tiled<Dq, Hq, 1><<<dim3(Hq/256, Dq/64, Eq), 256>>>(w1);
    conv_w_tiled<Hq, Dq, 2><<<dim3(Dq/256, Hq/64, Eq), 256>>>(w2);

    ffn_mma<1><<<dim3(Hq/256, 3, Eq*Bq), FFN_THREADS, SMEM_FFN>>>(b1);
    ffn_mma<2><<<dim3(Dq/256, 3, Eq*Bq), FFN_THREADS, SMEM_FFN>>>(b2);

    combine_kernel<<<NTOK, 256>>>(out);
}